// round 7
// baseline (speedup 1.0000x reference)
#include <cuda_runtime.h>
#include <cstdint>

// ---------------- problem constants ----------------
#define WRANKS 8
#define MDIM   4096
#define NDIM   4096
#define KDIM   1792

// ---------------- tile config ----------------
#define BM 128
#define BN 128
#define BK 32
#define NTHREADS 256
#define STAGES 3
#define TOTAL_STAGES ((WRANKS * KDIM) / BK)   // 448
#define STAGES_PER_RANK (KDIM / BK)           // 56

// smem row pitch in words: 36 -> 144B rows, 16B-aligned chunks, phase-conflict-free
#define SSTRIDE 36
#define TILE_WORDS (BM * SSTRIDE)             // 4608
#define STAGE_WORDS (2 * TILE_WORDS)
#define DYN_SMEM (STAGES * STAGE_WORDS * 4)   // 110592 B -> 2 CTAs/SM

// ---------------- tf32 scratch (pre-rounded, k-permuted operands) ----------------
// Within each 32-k block, element k (k = t + 4j, t=0..3, j=0..7) is stored at
// position p = t*8 + j. This makes each MMA thread's 8 fragment words for the
// whole BK tile contiguous -> LDS.128 fragment loads.
__device__ __align__(16) unsigned g_a_tf32[(size_t)WRANKS * MDIM * KDIM];
__device__ __align__(16) unsigned g_b_tf32[(size_t)WRANKS * NDIM * KDIM];

// ---------------- helpers ----------------
__device__ __forceinline__ unsigned f2tf32(float x) {
    unsigned r;
    asm("cvt.rna.tf32.f32 %0, %1;" : "=r"(r) : "f"(x));
    return r;
}

__device__ __forceinline__ uint32_t smem_to_u32(const void* p) {
    uint32_t a;
    asm("{ .reg .u64 t; cvta.to.shared.u64 t, %1; cvt.u32.u64 %0, t; }" : "=r"(a) : "l"(p));
    return a;
}

__device__ __forceinline__ void cp_async16(uint32_t dst, const void* src) {
    asm volatile("cp.async.cg.shared.global [%0], [%1], 16;" :: "r"(dst), "l"(src));
}
#define CP_COMMIT() asm volatile("cp.async.commit_group;" ::: "memory")
#define CP_WAIT(n)  asm volatile("cp.async.wait_group %0;" :: "n"(n) : "memory")

__device__ __forceinline__ void mma_tf32_m16n8k8(float c[4],
                                                 unsigned a0, unsigned a1, unsigned a2, unsigned a3,
                                                 unsigned b0, unsigned b1) {
    asm volatile(
        "mma.sync.aligned.m16n8k8.row.col.f32.tf32.tf32.f32 "
        "{%0,%1,%2,%3}, {%4,%5,%6,%7}, {%8,%9}, {%0,%1,%2,%3};\n"
        : "+f"(c[0]), "+f"(c[1]), "+f"(c[2]), "+f"(c[3])
        : "r"(a0), "r"(a1), "r"(a2), "r"(a3), "r"(b0), "r"(b1));
}

// ---------------- pass 1: fp32 -> tf32(RNA), k-permuted ----------------
// One thread per 32-k block: read 8 float4, permute in registers, write 8 uint4.
// out word p (p=0..31) = cvt(in word ((p>>3) + ((p&7)<<2)))
__global__ void __launch_bounds__(256) convert_tf32_perm_kernel(
    const float4* __restrict__ a, const float4* __restrict__ b,
    uint4* __restrict__ oa, uint4* __restrict__ ob)
{
    const size_t nblk = (size_t)WRANKS * MDIM * KDIM / 32;
    const size_t stride = (size_t)gridDim.x * blockDim.x;
    for (size_t blk = (size_t)blockIdx.x * blockDim.x + threadIdx.x; blk < nblk; blk += stride) {
        unsigned u[32];
        {
            const float4* src = a + blk * 8;
            #pragma unroll
            for (int q = 0; q < 8; q++) {
                float4 v = src[q];
                u[q * 4 + 0] = f2tf32(v.x); u[q * 4 + 1] = f2tf32(v.y);
                u[q * 4 + 2] = f2tf32(v.z); u[q * 4 + 3] = f2tf32(v.w);
            }
            uint4* dst = oa + blk * 8;
            #pragma unroll
            for (int q = 0; q < 8; q++) {
                uint4 o;
                o.x = u[((q * 4 + 0) >> 3) + (((q * 4 + 0) & 7) << 2)];
                o.y = u[((q * 4 + 1) >> 3) + (((q * 4 + 1) & 7) << 2)];
                o.z = u[((q * 4 + 2) >> 3) + (((q * 4 + 2) & 7) << 2)];
                o.w = u[((q * 4 + 3) >> 3) + (((q * 4 + 3) & 7) << 2)];
                dst[q] = o;
            }
        }
        {
            const float4* src = b + blk * 8;
            #pragma unroll
            for (int q = 0; q < 8; q++) {
                float4 v = src[q];
                u[q * 4 + 0] = f2tf32(v.x); u[q * 4 + 1] = f2tf32(v.y);
                u[q * 4 + 2] = f2tf32(v.z); u[q * 4 + 3] = f2tf32(v.w);
            }
            uint4* dst = ob + blk * 8;
            #pragma unroll
            for (int q = 0; q < 8; q++) {
                uint4 o;
                o.x = u[((q * 4 + 0) >> 3) + (((q * 4 + 0) & 7) << 2)];
                o.y = u[((q * 4 + 1) >> 3) + (((q * 4 + 1) & 7) << 2)];
                o.z = u[((q * 4 + 2) >> 3) + (((q * 4 + 2) & 7) << 2)];
                o.w = u[((q * 4 + 3) >> 3) + (((q * 4 + 3) & 7) << 2)];
                dst[q] = o;
            }
        }
    }
}

// ---------------- pass 2: pipelined tf32 mma.sync GEMM + fused all-reduce ----------------
extern __shared__ unsigned dsm[];

__global__ void __launch_bounds__(NTHREADS, 2)
gemm_ar_tf32_pipe(const unsigned* __restrict__ ga,   // [W, M, K] tf32 bits, k-permuted
                  const unsigned* __restrict__ gb,   // [W, N, K] tf32 bits, k-permuted
                  float* __restrict__ out)           // [M, N]
{
    const int tid  = threadIdx.x;
    const int warp = tid >> 5;
    const int lane = tid & 31;
    const int g    = lane >> 2;   // 0..7
    const int t    = lane & 3;    // 0..3

    // grid swizzle: 8-wide N-tile groups (B stays L2-resident across M sweep)
    const int GW = 8;
    const int MT = MDIM / BM;  // 32
    int gid   = blockIdx.x;
    int group = gid / (GW * MT);
    int rem   = gid % (GW * MT);
    int mt    = rem / GW;
    int nt    = group * GW + (rem % GW);
    const int m0 = mt * BM;
    const int n0 = nt * BN;

    const int wm = warp & 3;   // 4x2 warps, each 32(M) x 64(N)
    const int wn = warp >> 2;

    // staging coords: idx = tid + i*256 -> row = idx/8, chunk = idx%8
    const int row0  = tid >> 3;
    const int chunk = tid & 7;

    const uint32_t smem_u = smem_to_u32(dsm);

    float acc[2][8][4];
    #pragma unroll
    for (int im = 0; im < 2; im++)
        #pragma unroll
        for (int in = 0; in < 8; in++)
            #pragma unroll
            for (int j = 0; j < 4; j++)
                acc[im][in][j] = 0.0f;

    auto issue = [&](int s, int buf) {
        const int r  = s / STAGES_PER_RANK;
        const int kk = (s % STAGES_PER_RANK) * BK;
        const unsigned* Ab = ga + ((size_t)r * MDIM + m0) * KDIM + kk + chunk * 4;
        const unsigned* Bb = gb + ((size_t)r * NDIM + n0) * KDIM + kk + chunk * 4;
        const uint32_t abase = smem_u + (buf * STAGE_WORDS) * 4;
        const uint32_t bbase = abase + TILE_WORDS * 4;
        #pragma unroll
        for (int i = 0; i < 4; i++) {
            const int row = row0 + i * 32;
            cp_async16(abase + (row * SSTRIDE + chunk * 4) * 4, Ab + (size_t)row * KDIM);
            cp_async16(bbase + (row * SSTRIDE + chunk * 4) * 4, Bb + (size_t)row * KDIM);
        }
        CP_COMMIT();
    };

    #pragma unroll
    for (int s = 0; s < STAGES - 1; s++) issue(s, s);

    int buf = 0;
    for (int s = 0; s < TOTAL_STAGES; s++) {
        CP_WAIT(STAGES - 2);
        __syncthreads();   // also orders prev iteration's reads before refill below

        if (s + STAGES - 1 < TOTAL_STAGES)
            issue(s + STAGES - 1, (buf + STAGES - 1) % STAGES);
        else
            CP_COMMIT();   // keep group accounting aligned

        const unsigned* As = dsm + buf * STAGE_WORDS;
        const unsigned* Bs = As + TILE_WORDS;

        // two halves: h=0 covers k8 steps {0,1}, h=1 covers {2,3}
        #pragma unroll
        for (int h = 0; h < 2; h++) {
            uint4 av[2][2];
            #pragma unroll
            for (int im = 0; im < 2; im++) {
                const int r0 = wm * 32 + im * 16 + g;
                av[im][0] = *(const uint4*)(As + r0 * SSTRIDE + t * 8 + h * 4);
                av[im][1] = *(const uint4*)(As + (r0 + 8) * SSTRIDE + t * 8 + h * 4);
            }
            uint4 bv[8];
            #pragma unroll
            for (int in = 0; in < 8; in++) {
                const int c0 = wn * 64 + in * 8 + g;
                bv[in] = *(const uint4*)(Bs + c0 * SSTRIDE + t * 8 + h * 4);
            }
            // kl = 0 uses (.x, .y); kl = 1 uses (.z, .w)
            #pragma unroll
            for (int im = 0; im < 2; im++)
                #pragma unroll
                for (int in = 0; in < 8; in++)
                    mma_tf32_m16n8k8(acc[im][in],
                                     av[im][0].x, av[im][1].x, av[im][0].y, av[im][1].y,
                                     bv[in].x, bv[in].y);
            #pragma unroll
            for (int im = 0; im < 2; im++)
                #pragma unroll
                for (int in = 0; in < 8; in++)
                    mma_tf32_m16n8k8(acc[im][in],
                                     av[im][0].z, av[im][1].z, av[im][0].w, av[im][1].w,
                                     bv[in].z, bv[in].w);
        }

        if (++buf == STAGES) buf = 0;
    }

    // ---- epilogue ----
    const int m_base = m0 + wm * 32;
    const int n_base = n0 + wn * 64;
    #pragma unroll
    for (int im = 0; im < 2; im++) {
        #pragma unroll
        for (int in = 0; in < 8; in++) {
            int rr = m_base + im * 16 + g;
            int cc = n_base + in * 8 + t * 2;
            *(float2*)(out + (size_t)rr * NDIM + cc) =
                make_float2(acc[im][in][0], acc[im][in][1]);
            *(float2*)(out + (size_t)(rr + 8) * NDIM + cc) =
                make_float2(acc[im][in][2], acc[im][in][3]);
        }
    }
}

// ---------------- host launch ----------------
extern "C" void kernel_launch(void* const* d_in, const int* in_sizes, int n_in,
                              void* d_out, int out_size) {
    const float* a = (const float*)d_in[0];
    const float* b = (const float*)d_in[1];
    float* out = (float*)d_out;

    void *pa = nullptr, *pb = nullptr;
    cudaGetSymbolAddress(&pa, g_a_tf32);
    cudaGetSymbolAddress(&pb, g_b_tf32);

    // pass 1: round to tf32 (RNA) + k-permute for LDS.128 fragment loads
    convert_tf32_perm_kernel<<<2048, 256>>>((const float4*)a, (const float4*)b,
                                            (uint4*)pa, (uint4*)pb);

    // pass 2: pipelined GEMM, rank all-reduce fused into the K loop
    cudaFuncSetAttribute(gemm_ar_tf32_pipe,
                         cudaFuncAttributeMaxDynamicSharedMemorySize, DYN_SMEM);
    const int grid = (MDIM / BM) * (NDIM / BN);   // 1024
    gemm_ar_tf32_pipe<<<grid, NTHREADS, DYN_SMEM>>>(
        (const unsigned*)pa, (const unsigned*)pb, out);
}

// round 9
// speedup vs baseline: 1.2586x; 1.2586x over previous
#include <cuda_runtime.h>
#include <cstdint>

// ---------------- problem constants ----------------
#define WRANKS 8
#define MDIM   4096
#define NDIM   4096
#define KDIM   1792

// ---------------- tile config ----------------
#define BM 128
#define BN 128
#define BK 32
#define NTHREADS 256
#define STAGES 3
#define TOTAL_STAGES ((WRANKS * KDIM) / BK)   // 448
#define STAGES_PER_RANK (KDIM / BK)           // 56

// smem row pitch in words: 36 -> 144B rows; 16B chunks aligned; ldmatrix rows
// stride 4 words mod 32 -> each 8-row matrix tiles all 32 banks (conflict-free)
#define SSTRIDE 36
#define TILE_WORDS (BM * SSTRIDE)             // 4608
#define STAGE_WORDS (2 * TILE_WORDS)
#define DYN_SMEM (STAGES * STAGE_WORDS * 4)   // 110592 B -> 2 CTAs/SM

// ---------------- tf32 scratch (pre-rounded operands) ----------------
__device__ __align__(16) unsigned g_a_tf32[(size_t)WRANKS * MDIM * KDIM];
__device__ __align__(16) unsigned g_b_tf32[(size_t)WRANKS * NDIM * KDIM];

// ---------------- helpers ----------------
__device__ __forceinline__ unsigned f2tf32(float x) {
    unsigned r;
    asm("cvt.rna.tf32.f32 %0, %1;" : "=r"(r) : "f"(x));
    return r;
}

__device__ __forceinline__ uint32_t smem_to_u32(const void* p) {
    uint32_t a;
    asm("{ .reg .u64 t; cvta.to.shared.u64 t, %1; cvt.u32.u64 %0, t; }" : "=r"(a) : "l"(p));
    return a;
}

__device__ __forceinline__ void cp_async16(uint32_t dst, const void* src) {
    asm volatile("cp.async.cg.shared.global [%0], [%1], 16;" :: "r"(dst), "l"(src));
}
#define CP_COMMIT() asm volatile("cp.async.commit_group;" ::: "memory")
#define CP_WAIT(n)  asm volatile("cp.async.wait_group %0;" :: "n"(n) : "memory")

// ldmatrix: 4 independent dst regs, canonical mma.sync fragment layout (no MOV fixup)
__device__ __forceinline__ void ldsm_x4(unsigned& r0, unsigned& r1, unsigned& r2, unsigned& r3,
                                        uint32_t addr) {
    asm volatile("ldmatrix.sync.aligned.m8n8.x4.shared.b16 {%0,%1,%2,%3}, [%4];"
                 : "=r"(r0), "=r"(r1), "=r"(r2), "=r"(r3) : "r"(addr));
}

__device__ __forceinline__ void mma_tf32_m16n8k8(float c[4], const unsigned a[4],
                                                 unsigned b0, unsigned b1) {
    asm volatile(
        "mma.sync.aligned.m16n8k8.row.col.f32.tf32.tf32.f32 "
        "{%0,%1,%2,%3}, {%4,%5,%6,%7}, {%8,%9}, {%0,%1,%2,%3};\n"
        : "+f"(c[0]), "+f"(c[1]), "+f"(c[2]), "+f"(c[3])
        : "r"(a[0]), "r"(a[1]), "r"(a[2]), "r"(a[3]), "r"(b0), "r"(b1));
}

// ---------------- pass 1: fp32 -> tf32(RNA) bits (simple, coalesced) ----------------
__global__ void __launch_bounds__(256) convert_tf32_kernel(
    const float4* __restrict__ a, const float4* __restrict__ b,
    uint4* __restrict__ oa, uint4* __restrict__ ob)
{
    const size_t n4 = (size_t)WRANKS * MDIM * KDIM / 4;
    size_t stride = (size_t)gridDim.x * blockDim.x;
    for (size_t i = (size_t)blockIdx.x * blockDim.x + threadIdx.x; i < n4; i += stride) {
        float4 va = a[i];
        uint4 ua = { f2tf32(va.x), f2tf32(va.y), f2tf32(va.z), f2tf32(va.w) };
        oa[i] = ua;
        float4 vb = b[i];
        uint4 ub = { f2tf32(vb.x), f2tf32(vb.y), f2tf32(vb.z), f2tf32(vb.w) };
        ob[i] = ub;
    }
}

// ---------------- pass 2: pipelined tf32 mma.sync GEMM + fused all-reduce ----------------
extern __shared__ unsigned dsm[];

__global__ void __launch_bounds__(NTHREADS, 2)
gemm_ar_tf32_pipe(const unsigned* __restrict__ ga,   // [W, M, K] tf32 bits
                  const unsigned* __restrict__ gb,   // [W, N, K] tf32 bits
                  float* __restrict__ out)           // [M, N]
{
    const int tid  = threadIdx.x;
    const int warp = tid >> 5;
    const int lane = tid & 31;
    const int g    = lane >> 2;
    const int t    = lane & 3;

    // grid swizzle: 8-wide N-tile groups (B stays L2-resident across M sweep)
    const int GW = 8;
    const int MT = MDIM / BM;  // 32
    int gid   = blockIdx.x;
    int group = gid / (GW * MT);
    int rem   = gid % (GW * MT);
    int mt    = rem / GW;
    int nt    = group * GW + (rem % GW);
    const int m0 = mt * BM;
    const int n0 = nt * BN;

    const int wm = warp & 3;   // 4x2 warps, each 32(M) x 64(N)
    const int wn = warp >> 2;

    // staging coords: idx = tid + i*256 -> row = idx/8, chunk = idx%8
    const int row0  = tid >> 3;
    const int chunk = tid & 7;

    const uint32_t smem_u = smem_to_u32(dsm);

    // ---- ldmatrix per-lane byte offsets (within a tile) ----
    // A, im half: matrices {rows 0-7 | 8-15} x {colword +0 | +4}
    //   lane -> row = lane&15, colword = (lane>>4)*4
    // B, in-pair p: matrices {n-rows 0-7 col+0 | col+4 | n-rows 8-15 col+0 | col+4}
    //   lane -> row = (lane&7) + ((lane>>4)<<3), colword = ((lane>>3)&1)*4
    uint32_t a_off[2], b_off[4];
    {
        const int arow = lane & 15;
        const int acol = (lane >> 4) * 4;
        #pragma unroll
        for (int im = 0; im < 2; im++)
            a_off[im] = ((wm * 32 + im * 16 + arow) * SSTRIDE + acol) * 4;
        const int brow = (lane & 7) + ((lane >> 4) << 3);
        const int bcol = ((lane >> 3) & 1) * 4;
        #pragma unroll
        for (int p = 0; p < 4; p++)
            b_off[p] = ((wn * 64 + p * 16 + brow) * SSTRIDE + bcol) * 4 + TILE_WORDS * 4;
    }

    float acc[2][8][4];
    #pragma unroll
    for (int im = 0; im < 2; im++)
        #pragma unroll
        for (int in = 0; in < 8; in++)
            #pragma unroll
            for (int j = 0; j < 4; j++)
                acc[im][in][j] = 0.0f;

    auto issue = [&](int s, int buf) {
        const int r  = s / STAGES_PER_RANK;
        const int kk = (s % STAGES_PER_RANK) * BK;
        const unsigned* Ab = ga + ((size_t)r * MDIM + m0) * KDIM + kk + chunk * 4;
        const unsigned* Bb = gb + ((size_t)r * NDIM + n0) * KDIM + kk + chunk * 4;
        const uint32_t abase = smem_u + (buf * STAGE_WORDS) * 4;
        const uint32_t bbase = abase + TILE_WORDS * 4;
        #pragma unroll
        for (int i = 0; i < 4; i++) {
            const int row = row0 + i * 32;
            cp_async16(abase + (row * SSTRIDE + chunk * 4) * 4, Ab + (size_t)row * KDIM);
            cp_async16(bbase + (row * SSTRIDE + chunk * 4) * 4, Bb + (size_t)row * KDIM);
        }
        CP_COMMIT();
    };

    #pragma unroll
    for (int s = 0; s < STAGES - 1; s++) issue(s, s);

    int buf = 0;
    for (int s = 0; s < TOTAL_STAGES; s++) {
        CP_WAIT(STAGES - 2);
        __syncthreads();   // orders prev iteration's reads before refill below

        if (s + STAGES - 1 < TOTAL_STAGES)
            issue(s + STAGES - 1, (buf + STAGES - 1) % STAGES);
        else
            CP_COMMIT();   // keep group accounting aligned

        const uint32_t tbase = smem_u + (buf * STAGE_WORDS) * 4;

        #pragma unroll
        for (int ks = 0; ks < 4; ks++) {
            const uint32_t ko = ks * 32;   // 8 words per k8 step
            unsigned af[2][4];
            ldsm_x4(af[0][0], af[0][1], af[0][2], af[0][3], tbase + a_off[0] + ko);
            ldsm_x4(af[1][0], af[1][1], af[1][2], af[1][3], tbase + a_off[1] + ko);
            unsigned bf[4][4];
            #pragma unroll
            for (int p = 0; p < 4; p++)
                ldsm_x4(bf[p][0], bf[p][1], bf[p][2], bf[p][3], tbase + b_off[p] + ko);

            #pragma unroll
            for (int im = 0; im < 2; im++)
                #pragma unroll
                for (int p = 0; p < 4; p++) {
                    mma_tf32_m16n8k8(acc[im][p * 2 + 0], af[im], bf[p][0], bf[p][1]);
                    mma_tf32_m16n8k8(acc[im][p * 2 + 1], af[im], bf[p][2], bf[p][3]);
                }
        }

        if (++buf == STAGES) buf = 0;
    }

    // ---- epilogue ----
    const int m_base = m0 + wm * 32;
    const int n_base = n0 + wn * 64;
    #pragma unroll
    for (int im = 0; im < 2; im++) {
        #pragma unroll
        for (int in = 0; in < 8; in++) {
            int rr = m_base + im * 16 + g;
            int cc = n_base + in * 8 + t * 2;
            *(float2*)(out + (size_t)rr * NDIM + cc) =
                make_float2(acc[im][in][0], acc[im][in][1]);
            *(float2*)(out + (size_t)(rr + 8) * NDIM + cc) =
                make_float2(acc[im][in][2], acc[im][in][3]);
        }
    }
}

// ---------------- host launch ----------------
extern "C" void kernel_launch(void* const* d_in, const int* in_sizes, int n_in,
                              void* d_out, int out_size) {
    const float* a = (const float*)d_in[0];
    const float* b = (const float*)d_in[1];
    float* out = (float*)d_out;

    void *pa = nullptr, *pb = nullptr;
    cudaGetSymbolAddress(&pa, g_a_tf32);
    cudaGetSymbolAddress(&pb, g_b_tf32);

    // pass 1: round both operands to tf32 (RNA) so HMMA truncation is exact
    convert_tf32_kernel<<<2048, 256>>>((const float4*)a, (const float4*)b,
                                       (uint4*)pa, (uint4*)pb);

    // pass 2: pipelined GEMM, rank all-reduce fused into the K loop
    cudaFuncSetAttribute(gemm_ar_tf32_pipe,
                         cudaFuncAttributeMaxDynamicSharedMemorySize, DYN_SMEM);
    const int grid = (MDIM / BM) * (NDIM / BN);   // 1024
    gemm_ar_tf32_pipe<<<grid, NTHREADS, DYN_SMEM>>>(
        (const unsigned*)pa, (const unsigned*)pb, out);
}